// round 6
// baseline (speedup 1.0000x reference)
#include <cuda_runtime.h>

#define BB 16
#define SS 2048
#define NC 8
#define NT 256
#define NW (NT / 32)          // 8 warps
#define RPB 8                 // blocks per row
#define GRIDN (BB * RPB)      // 128 CTAs
#define LOG2E 1.4426950408889634f
#define T1V 100.0f
#define EPSV 1e-8f

__device__ __forceinline__ float ex2(float x) {
    float y; asm("ex2.approx.ftz.f32 %0, %1;" : "=f"(y) : "f"(x)); return y;
}
__device__ __forceinline__ float flog(float x) {
    float y; asm("lg2.approx.ftz.f32 %0, %1;" : "=f"(y) : "f"(x));
    return y * 0.6931471805599453f;
}

// Cross-block state (no allocations allowed). Replay-safe.
__device__ double   g_partials[GRIDN];
__device__ unsigned g_ticket;            // last block resets to 0 each run

__global__ __launch_bounds__(NT)
void hawkes_kernel(const float* __restrict__ ts,
                   const int*   __restrict__ ms,
                   const float* __restrict__ mu,
                   const float* __restrict__ alphas,
                   const float* __restrict__ beta,
                   float*       __restrict__ out)
{
    __shared__ float  AB[NC * NC];        // alphas[m][c] * beta[c]
    __shared__ float  colsum[NC];
    __shared__ float  mu_s[NC];
    __shared__ float  beta_s[NC];
    __shared__ float  Pred[NW][NC + 1];   // per-warp prefix-reduction partials
    __shared__ float  bpref[NC];          // block-exclusive prefix (anchored Ta)
    __shared__ float  Wagg[NW][NC + 1];   // per-warp scan totals
    __shared__ float  WT[NW];             // per-warp anchor timestamps
    __shared__ float  inclW[NW][NC + 1];  // inclusive warp-level prefix
    __shared__ double wsum[NW];

    const int bx   = blockIdx.x;
    const int row  = bx >> 3;             // / RPB
    const int blk  = bx & (RPB - 1);
    const int t    = threadIdx.x;
    const int w    = t >> 5;
    const int lane = t & 31;

    const float* tsr = ts + row * SS;
    const int*   msr = ms + row * SS;

    // ---- Own event (coalesced) + block anchor ----
    const int   li    = blk * NT + t;     // index within row
    const float ti    = tsr[li];
    const int   m     = msr[li];
    const bool  valid = (ti > 0.f);
    const float Ta    = tsr[blk * NT];    // first event of this block (broadcast, L1)

    // ---- Parameter staging ----
    if (t < NC * NC) AB[t] = alphas[t] * beta[t & (NC - 1)];
    if (t < NC) {
        float s = 0.f;
        #pragma unroll
        for (int k = 0; k < NC; k++) s += alphas[k * NC + t];
        colsum[t] = s;
        mu_s[t]   = mu[t];
        beta_s[t] = beta[t];
    }
    __syncthreads();
    float bl2[NC];
    #pragma unroll
    for (int c = 0; c < NC; c++) bl2[c] = beta_s[c] * LOG2E;

    // ---- Redundant prefix REDUCTION over all prior events, anchored at Ta ----
    // (prior t_j <= Ta since timestamps are sorted => exponents <= 0)
    float P[NC];
    #pragma unroll
    for (int c = 0; c < NC; c++) P[c] = 0.f;
    for (int k = 0; k < blk; k++) {          // <= 7 iterations, coalesced loads
        float tj = tsr[k * NT + t];
        int   mj = msr[k * NT + t];
        if (tj > 0.f) P[mj] += ex2(bl2[mj] * (tj - Ta));
    }
    // warp tree-reduce each class
    #pragma unroll
    for (int off = 16; off > 0; off >>= 1) {
        #pragma unroll
        for (int c = 0; c < NC; c++)
            P[c] += __shfl_down_sync(0xffffffffu, P[c], off);
    }
    if (lane == 0) {
        #pragma unroll
        for (int c = 0; c < NC; c++) Pred[w][c] = P[c];
    }

    // ---- One-hot element for intra-block scan, anchored at own timestamp ----
    float V[NC];
    #pragma unroll
    for (int c = 0; c < NC; c++) V[c] = 0.f;
    if (valid) V[m] = 1.f;

    // ---- Warp-level inclusive Kogge-Stone (registers, shfl) ----
    #pragma unroll
    for (int off = 1; off < 32; off <<= 1) {
        float Tp = __shfl_up_sync(0xffffffffu, ti, off);
        float Vp[NC];
        #pragma unroll
        for (int c = 0; c < NC; c++) Vp[c] = __shfl_up_sync(0xffffffffu, V[c], off);
        if (lane >= off) {
            #pragma unroll
            for (int c = 0; c < NC; c++)
                V[c] += Vp[c] * ex2(bl2[c] * (Tp - ti));   // Tp <= ti (sorted)
        }
    }
    if (lane == 31) {
        #pragma unroll
        for (int c = 0; c < NC; c++) Wagg[w][c] = V[c];
        WT[w] = ti;
    }
    __syncthreads();

    // ---- Small serial jobs in parallel by the first 16 threads ----
    if (t < NC) {
        // inclusive scan over the 8 warp aggregates (class t)
        const int c = t;
        float run = 0.f, Tprev = WT[0];
        #pragma unroll
        for (int ww = 0; ww < NW; ww++) {
            float Tw = WT[ww];
            run = Wagg[ww][c] + run * ex2(bl2[c] * (Tprev - Tw));
            inclW[ww][c] = run;
            Tprev = Tw;
        }
    } else if (t < 2 * NC) {
        // finish block-prefix reduction (class t-8)
        const int c = t - NC;
        float s = 0.f;
        #pragma unroll
        for (int ww = 0; ww < NW; ww++) s += Pred[ww][c];
        bpref[c] = s;
    }
    __syncthreads();

    // ---- Fold warp-exclusive prefix and block prefix into own inclusive value ----
    if (w > 0) {
        const float Tp = WT[w - 1];
        #pragma unroll
        for (int c = 0; c < NC; c++)
            V[c] += inclW[w - 1][c] * ex2(bl2[c] * (Tp - ti));
    }
    if (blk > 0) {
        #pragma unroll
        for (int c = 0; c < NC; c++)
            V[c] += bpref[c] * ex2(bl2[c] * (Ta - ti));    // Ta <= ti
    }

    // ---- Per-event log-likelihood term (no replay loop needed) ----
    double acc = 0.0;
    if (valid) {
        V[m] -= 1.f;                      // exclude own event (strict j < i)
        float lam = mu_s[m];
        #pragma unroll
        for (int c = 0; c < NC; c++) lam += AB[m * NC + c] * V[c];
        float contrib = flog(lam + EPSV)
                      - colsum[m] * (1.f - ex2(-bl2[m] * (T1V - ti)));
        acc = (double)contrib;
    }

    // ---- Reductions: warp shfl -> block -> ticketed global finalize ----
    #pragma unroll
    for (int off = 16; off > 0; off >>= 1)
        acc += __shfl_down_sync(0xffffffffu, acc, off);
    if (lane == 0) wsum[w] = acc;
    __syncthreads();

    if (t == 0) {
        double s = 0.0;
        #pragma unroll
        for (int ww = 0; ww < NW; ww++) s += wsum[ww];
        g_partials[bx] = s;
        __threadfence();
        unsigned tk = atomicAdd(&g_ticket, 1u);
        if (tk == GRIDN - 1) {            // last block finalizes, fixed order
            __threadfence();
            double tot = 0.0;
            for (int i = 0; i < GRIDN; i++) tot += __ldcg(&g_partials[i]);
            double musum = 0.0;
            #pragma unroll
            for (int c = 0; c < NC; c++) musum += (double)mu_s[c];
            out[0] = (float)(tot - musum * (double)T1V);
            __threadfence();
            g_ticket = 0;                 // reset for next graph replay
        }
    }
}

extern "C" void kernel_launch(void* const* d_in, const int* in_sizes, int n_in,
                              void* d_out, int out_size)
{
    const float* ts     = (const float*)d_in[0];
    const int*   ms     = (const int*)  d_in[1];
    const float* mu     = (const float*)d_in[2];
    const float* alphas = (const float*)d_in[3];
    const float* beta   = (const float*)d_in[4];
    float*       out    = (float*)d_out;

    hawkes_kernel<<<GRIDN, NT>>>(ts, ms, mu, alphas, beta, out);
}

// round 9
// speedup vs baseline: 1.2765x; 1.2765x over previous
#include <cuda_runtime.h>

#define BB 16
#define SS 2048
#define NC 8
#define NT 512
#define NW (NT / 32)           // 16 warps
#define CHUNK 4                // SS / NT
#define LOG2E 1.4426950408889634f
#define T1V 100.0f
#define EPSV 1e-8f

__device__ __forceinline__ float ex2(float x) {
    float y; asm("ex2.approx.ftz.f32 %0, %1;" : "=f"(y) : "f"(x)); return y;
}
__device__ __forceinline__ float flog(float x) {
    float y; asm("lg2.approx.ftz.f32 %0, %1;" : "=f"(y) : "f"(x));
    return y * 0.6931471805599453f;
}

// Cross-block state (no allocations). Replay-safe.
__device__ double   g_partials[BB];
__device__ unsigned g_ticket;          // last block resets to 0 each run

__global__ __launch_bounds__(NT)
void hawkes_kernel(const float* __restrict__ ts,
                   const int*   __restrict__ ms,
                   const float* __restrict__ mu,
                   const float* __restrict__ alphas,
                   const float* __restrict__ beta,
                   float*       __restrict__ out)
{
    __shared__ float  AB[NC * NC];       // alphas[m][c] * beta[c]
    __shared__ float  colsum[NC];        // sum_k alphas[k][c]
    __shared__ float  mu_s[NC];
    __shared__ float  Wagg[NW][NC + 1];  // per-warp channel sums (anchored at own Tw)
    __shared__ float  WT[NW];            // per-warp anchor timestamps
    __shared__ float  inclW[NW][NC + 1]; // inclusive cross-warp prefix
    __shared__ double wsum[NW];

    const int b    = blockIdx.x;         // one block per batch row
    const int t    = threadIdx.x;
    const int w    = t >> 5;
    const int lane = t & 31;

    // ---- Per-thread params (const cache; no barrier needed) ----
    float bl2[NC];
    #pragma unroll
    for (int c = 0; c < NC; c++) bl2[c] = __ldg(&beta[c]) * LOG2E;

    // ---- Stage small params into smem (covered by the scan barrier below) ----
    if (t < NC * NC) AB[t] = alphas[t] * __ldg(&beta[t & (NC - 1)]);
    if (t < NC) {
        float s = 0.f;
        #pragma unroll
        for (int k = 0; k < NC; k++) s += alphas[k * NC + t];
        colsum[t] = s;
        mu_s[t]   = mu[t];
    }

    // ---- Load this thread's 4 events (LDG.128, coalesced) ----
    float tloc[CHUNK];
    int   mloc[CHUNK];
    *(float4*)tloc = ((const float4*)(ts + b * SS))[t];
    *(int4*)mloc   = ((const int4*)  (ms + b * SS))[t];

    // Warp anchor = last event time in warp (sorted ascending)
    const float Tw = __shfl_sync(0xffffffffu, tloc[CHUNK - 1], 31);

    // ---- Anchored event weights (1 ex2 per event, independent) ----
    float ev[CHUNK];
    #pragma unroll
    for (int j = 0; j < CHUNK; j++)
        ev[j] = (tloc[j] > 0.f) ? ex2(bl2[mloc[j]] * (tloc[j] - Tw)) : 0.f;

    // ---- Chunk channel sums ----
    float V[NC];
    #pragma unroll
    for (int c = 0; c < NC; c++) V[c] = 0.f;
    #pragma unroll
    for (int j = 0; j < CHUNK; j++) V[mloc[j]] += ev[j];

    // ---- Warp inclusive Kogge-Stone: PLAIN ADDS (common anchor) ----
    #pragma unroll
    for (int off = 1; off < 32; off <<= 1) {
        float Vp[NC];
        #pragma unroll
        for (int c = 0; c < NC; c++) Vp[c] = __shfl_up_sync(0xffffffffu, V[c], off);
        if (lane >= off) {
            #pragma unroll
            for (int c = 0; c < NC; c++) V[c] += Vp[c];
        }
    }
    if (lane == 31) {
        #pragma unroll
        for (int c = 0; c < NC; c++) Wagg[w][c] = V[c];
        WT[w] = Tw;
    }
    __syncthreads();

    // ---- Serial rescale-scan across 16 warps (thread c owns class c) ----
    if (t < NC) {
        const int c = t;
        float run = 0.f, Tprev = WT[0];
        #pragma unroll
        for (int ww = 0; ww < NW; ww++) {
            float Twk = WT[ww];
            run = Wagg[ww][c] + run * ex2(bl2[c] * (Tprev - Twk));  // Tprev <= Twk
            inclW[ww][c] = run;
            Tprev = Twk;
        }
    }
    __syncthreads();

    // ---- Exclusive prefix state S anchored at Tw ----
    float S[NC];
    {
        // chunk-exclusive within warp
        float Ve[NC];
        #pragma unroll
        for (int c = 0; c < NC; c++) {
            float p = __shfl_up_sync(0xffffffffu, V[c], 1);
            Ve[c] = (lane == 0) ? 0.f : p;
        }
        if (w > 0) {
            const float Tp = WT[w - 1];
            #pragma unroll
            for (int c = 0; c < NC; c++)
                S[c] = Ve[c] + inclW[w - 1][c] * ex2(bl2[c] * (Tp - Tw));
        } else {
            #pragma unroll
            for (int c = 0; c < NC; c++) S[c] = Ve[c];
        }
    }

    // ---- Per-event log-likelihood terms (independent, no serial replay) ----
    double acc = 0.0;
    #pragma unroll
    for (int j = 0; j < CHUNK; j++) {
        const float ti = tloc[j];
        const int   m  = mloc[j];
        if (ti > 0.f) {
            float lam = mu_s[m];
            #pragma unroll
            for (int c = 0; c < NC; c++)
                lam += AB[m * NC + c] * S[c] * ex2(bl2[c] * (Tw - ti)); // exponent >= 0, bounded
            float contrib = flog(lam + EPSV)
                          - colsum[m] * (1.f - ex2(-bl2[m] * (T1V - ti)));
            acc += (double)contrib;
        }
        S[m] += ev[j];   // event j becomes source for later events in chunk
    }

    // ---- Reductions: warp shfl -> block -> ticketed global finalize ----
    #pragma unroll
    for (int off = 16; off > 0; off >>= 1)
        acc += __shfl_down_sync(0xffffffffu, acc, off);
    if (lane == 0) wsum[w] = acc;
    __syncthreads();

    if (t == 0) {
        double s = 0.0;
        #pragma unroll
        for (int ww = 0; ww < NW; ww++) s += wsum[ww];
        g_partials[b] = s;
        __threadfence();
        unsigned tk = atomicAdd(&g_ticket, 1u);
        if (tk == BB - 1) {                  // last block finalizes, fixed order
            __threadfence();
            double tot = 0.0;
            #pragma unroll
            for (int i = 0; i < BB; i++) tot += __ldcg(&g_partials[i]);
            double musum = 0.0;
            #pragma unroll
            for (int c = 0; c < NC; c++) musum += (double)mu_s[c];
            out[0] = (float)(tot - musum * (double)T1V);
            __threadfence();
            g_ticket = 0;                    // reset for next graph replay
        }
    }
}

extern "C" void kernel_launch(void* const* d_in, const int* in_sizes, int n_in,
                              void* d_out, int out_size)
{
    const float* ts     = (const float*)d_in[0];
    const int*   ms     = (const int*)  d_in[1];
    const float* mu     = (const float*)d_in[2];
    const float* alphas = (const float*)d_in[3];
    const float* beta   = (const float*)d_in[4];
    float*       out    = (float*)d_out;

    hawkes_kernel<<<BB, NT>>>(ts, ms, mu, alphas, beta, out);
}